// round 15
// baseline (speedup 1.0000x reference)
#include <cuda_runtime.h>
#include <math.h>

#define BB 4
#define NN 1024
#define DD 1024
#define EE 32
#define HHH 4096

// ---------------- scratch (device globals; no allocation allowed) ----------
__device__ float g_logits[BB * NN * EE];            // 512 KB  [b,n,e]
__device__ float g_logitsT[BB * EE * NN];           // 512 KB  [b,e,n]
__device__ float g_combine[BB * NN * EE];           // 512 KB  [b,n,e]
__device__ float g_dispT[BB * EE * NN];             // 512 KB  [b,e,n]
__device__ float g_slots_part[4 * BB * EE * DD];    // 2 MB
__device__ float g_h[BB * EE * HHH];                // 2 MB
__device__ float g_eout_part[8 * BB * EE * DD];     // 4 MB
__device__ float g_eout[BB * EE * DD];              // 512 KB
__device__ float g_part_cw1[512];
__device__ float g_part_cw2[512];
__device__ float g_part_dw[128];

// ---------------- reduction helpers ----------------
__device__ __forceinline__ float warpSum(float v) {
    #pragma unroll
    for (int o = 16; o; o >>= 1) v += __shfl_xor_sync(0xffffffffu, v, o);
    return v;
}
__device__ __forceinline__ float warpMax(float v) {
    #pragma unroll
    for (int o = 16; o; o >>= 1) v = fmaxf(v, __shfl_xor_sync(0xffffffffu, v, o));
    return v;
}
__device__ float blockSum(float v) {
    __shared__ float sh[32];
    int lane = threadIdx.x & 31, wid = threadIdx.x >> 5;
    int nw = (blockDim.x + 31) >> 5;
    v = warpSum(v);
    if (lane == 0) sh[wid] = v;
    __syncthreads();
    float r = (threadIdx.x < (unsigned)nw) ? sh[threadIdx.x] : 0.f;
    if (wid == 0) {
        r = warpSum(r);
        if (lane == 0) sh[0] = r;
    }
    __syncthreads();
    r = sh[0];
    __syncthreads();
    return r;
}
__device__ float blockMax(float v) {
    __shared__ float sh[32];
    int lane = threadIdx.x & 31, wid = threadIdx.x >> 5;
    int nw = (blockDim.x + 31) >> 5;
    v = warpMax(v);
    if (lane == 0) sh[wid] = v;
    __syncthreads();
    float r = (threadIdx.x < (unsigned)nw) ? sh[threadIdx.x] : -INFINITY;
    if (wid == 0) {
        r = warpMax(r);
        if (lane == 0) sh[0] = r;
    }
    __syncthreads();
    r = sh[0];
    __syncthreads();
    return r;
}

__device__ __forceinline__ float gelu_exact(float x) {
    return 0.5f * x * (1.f + erff(x * 0.70710678118654752f));
}

// ---------------- 1. fused query-LN + logits --------------------------------
__global__ void k_logits_q(const float* __restrict__ x, const float* __restrict__ phi,
                           const float* __restrict__ kg, const float* __restrict__ kb,
                           const float* __restrict__ qg, const float* __restrict__ qb,
                           const float* __restrict__ lg, const float* __restrict__ lb,
                           const float* __restrict__ sc) {
    __shared__ float xs[64][64];
    __shared__ float qs[32][65];
    __shared__ float ts[64][33];
    __shared__ float s_mean[32], s_rs[32];
    int t = threadIdx.x;
    int b = blockIdx.x >> 4, nb = (blockIdx.x & 15) * 64;
    int e = t & 31, ng = t >> 5;
    int lane = t & 31, w = t >> 5;

    // LN stats: warp w handles experts w*4..w*4+3
    #pragma unroll
    for (int i = 0; i < 4; i++) {
        int ee = w * 4 + i;
        float s = 0.f, s2 = 0.f;
        #pragma unroll 8
        for (int k = 0; k < 32; k++) {
            int d = k * 32 + lane;
            float y = phi[ee * DD + d] * qg[d] + qb[d];
            s += y; s2 += y * y;
        }
        s = warpSum(s); s2 = warpSum(s2);
        if (lane == 0) {
            float m = s * (1.f / DD);
            s_mean[ee] = m;
            s_rs[ee] = rsqrtf(s2 * (1.f / DD) - m * m + 1e-5f);
        }
    }
    __syncthreads();
    float scale = sc[0];

    float acc[8] = {0, 0, 0, 0, 0, 0, 0, 0};
    for (int dc = 0; dc < 16; dc++) {
        int dbase = dc * 64;
        #pragma unroll
        for (int k = 0; k < 16; k++) {
            int idx = t + k * 256;
            int r = idx >> 6, c = idx & 63, d = dbase + c;
            xs[r][c] = x[((b << 10) + nb + r) * DD + d] * kg[d] + kb[d];
        }
        #pragma unroll
        for (int k = 0; k < 8; k++) {
            int idx = t + k * 256;
            int r = idx >> 6, c = idx & 63, d = dbase + c;
            float y = phi[r * DD + d] * qg[d] + qb[d];
            qs[r][c] = ((y - s_mean[r]) * s_rs[r] * lg[d] + lb[d]) * scale;
        }
        __syncthreads();
        #pragma unroll 4
        for (int dd = 0; dd < 64; dd++) {
            float qv = qs[e][dd];
            #pragma unroll
            for (int i = 0; i < 8; i++) acc[i] += xs[ng * 8 + i][dd] * qv;
        }
        __syncthreads();
    }
    #pragma unroll
    for (int i = 0; i < 8; i++) {
        g_logits[(((b << 10) + nb + ng * 8 + i) << 5) + e] = acc[i];
        ts[ng * 8 + i][e] = acc[i];
    }
    __syncthreads();
    #pragma unroll
    for (int k = 0; k < 8; k++) {
        int idx = t + k * 256;
        int ee = idx >> 6, n = idx & 63;
        g_logitsT[(((b << 5) + ee) << 10) + nb + n] = ts[n][ee];
    }
}

// ---------------- 2. fused softmaxes: dispatch (blocks 0-127) + combine ----
__global__ void k_softmaxes() {
    int t = threadIdx.x;
    if (blockIdx.x < 128) {
        // ---- dispatch softmax over N (coalesced via T layout) ----
        int be = blockIdx.x;          // be = b*32 + e
        int e = be & 31;
        float v[4];
        float mx = -INFINITY;
        #pragma unroll
        for (int k = 0; k < 4; k++) {
            int n = t + k * 256;
            v[k] = g_logitsT[(be << 10) + n];
            mx = fmaxf(mx, v[k]);
        }
        mx = blockMax(mx);
        float ls = 0.f;
        #pragma unroll
        for (int k = 0; k < 4; k++) { v[k] = expf(v[k] - mx); ls += v[k]; }
        float S = blockSum(ls);
        float inv = 1.f / S;
        float s1 = 0.f, s2 = 0.f;
        #pragma unroll
        for (int k = 0; k < 4; k++) {
            int n = t + k * 256;
            float dv = v[k] * inv;
            g_dispT[(be << 10) + n] = dv;
            s1 += dv;
            s2 += dv * dv;
        }
        float S1 = blockSum(s1);
        float S2 = blockSum(s2);
        if (t == 0) {
            float rsd = rsqrtf(S2 + 1e-9f);
            float sn = S1 * rsd;
            g_part_dw[be] = (e == 0) ? 0.f : sn * sn;
        }
    } else {
        // ---- combine softmax (warp per row) + cw metric partials ----
        int cb = blockIdx.x - 128;     // 0..511
        int lane = t & 31, w = t >> 5; // 8 warps
        int row = cb * 8 + w;          // row = b*1024 + n, 0..4095
        float v = g_logits[(row << 5) + lane];
        float m = warpMax(v);
        float p = expf(v - m);
        float s = warpSum(p);
        float cw = p / s;
        g_combine[(row << 5) + lane] = cw;
        float s2 = warpSum(cw * cw);
        float rs = rsqrtf(s2 + 1e-9f);
        float cf = cw * rs;
        float s1 = warpSum(cf);
        int n = row & 1023;
        float c2 = (n < 32 && lane == n) ? cf * s1 : 0.f;
        c2 = warpSum(c2);
        __shared__ float p1[8], p2[8];
        if (lane == 0) { p1[w] = s1 * s1; p2[w] = c2; }
        __syncthreads();
        if (w == 0 && lane == 0) {
            float a = 0.f, bb2 = 0.f;
            #pragma unroll
            for (int i = 0; i < 8; i++) { a += p1[i]; bb2 += p2[i]; }
            g_part_cw1[cb] = a;
            g_part_cw2[cb] = bb2;
        }
    }
}

// ---------------- 3. slots partials: sum_n dispT[b,e,n]*x[b,n,d] -----------
__global__ void k_slots(const float* __restrict__ x) {
    __shared__ float ws[64][33];
    int b = blockIdx.x, dt = blockIdx.y, nc = blockIdx.z;
    int t = threadIdx.x;
    int d = dt * 64 + (t & 63);
    int eb = (t >> 6) * 8;
    float acc[8] = {0, 0, 0, 0, 0, 0, 0, 0};
    for (int no = 0; no < 4; no++) {
        int nbase = nc * 256 + no * 64;
        #pragma unroll
        for (int k = 0; k < 8; k++) {
            int idx = t + k * 256;
            int ee = idx >> 6, n = idx & 63;
            ws[n][ee] = g_dispT[(((b << 5) + ee) << 10) + nbase + n];
        }
        __syncthreads();
        #pragma unroll 4
        for (int nn = 0; nn < 64; nn++) {
            float xv = __ldg(&x[(((b << 10) + nbase + nn) << 10) + d]);
            #pragma unroll
            for (int i = 0; i < 8; i++) acc[i] += ws[nn][eb + i] * xv;
        }
        __syncthreads();
    }
    #pragma unroll
    for (int i = 0; i < 8; i++)
        g_slots_part[nc * (BB * EE * DD) + (b * EE + eb + i) * DD + d] = acc[i];
}

// ---------------- 4. MLP1: h = gelu(slots @ w1 + b1), direct write ---------
// grid (32 e, 32 jt of 128), 256 thr. Warp dg handles d = dg mod 8;
// cross-warp reduce in smem, then b1 + gelu epilogue.
__global__ void k_mlp1(const float* __restrict__ w1, const float* __restrict__ b1) {
    __shared__ float ss[4][1024];                 // 16 KB
    __shared__ float4 red[8][32][4];              // 16 KB
    int e = blockIdx.x, jt = blockIdx.y, t = threadIdx.x;
    // prologue: fuse slots nc-reduce (slots_part is L2-resident)
    #pragma unroll
    for (int k = 0; k < 16; k++) {
        int idx = t + k * 256;
        int b = idx >> 10, d = idx & 1023;
        float s = 0.f;
        #pragma unroll
        for (int nc = 0; nc < 4; nc++)
            s += g_slots_part[nc * (BB * EE * DD) + (b * EE + e) * DD + d];
        ss[b][d] = s;
    }
    __syncthreads();
    int lane = t & 31, dg = t >> 5;
    int j = jt * 128 + lane * 4;
    const float* wbase = w1 + (size_t)e * DD * HHH;
    float4 a0 = {0,0,0,0}, a1 = {0,0,0,0}, a2 = {0,0,0,0}, a3 = {0,0,0,0};
    #pragma unroll 8
    for (int d = dg; d < 1024; d += 8) {
        float4 w = __ldcs((const float4*)(wbase + (size_t)d * HHH + j));
        float s0 = ss[0][d], s1 = ss[1][d], s2 = ss[2][d], s3 = ss[3][d];
        a0.x += s0 * w.x; a0.y += s0 * w.y; a0.z += s0 * w.z; a0.w += s0 * w.w;
        a1.x += s1 * w.x; a1.y += s1 * w.y; a1.z += s1 * w.z; a1.w += s1 * w.w;
        a2.x += s2 * w.x; a2.y += s2 * w.y; a2.z += s2 * w.z; a2.w += s2 * w.w;
        a3.x += s3 * w.x; a3.y += s3 * w.y; a3.z += s3 * w.z; a3.w += s3 * w.w;
    }
    red[dg][lane][0] = a0;
    red[dg][lane][1] = a1;
    red[dg][lane][2] = a2;
    red[dg][lane][3] = a3;
    __syncthreads();
    if (t < 128) {
        int b = t >> 5, jq = t & 31;
        float4 r = {0,0,0,0};
        #pragma unroll
        for (int g = 0; g < 8; g++) {
            float4 v = red[g][jq][b];
            r.x += v.x; r.y += v.y; r.z += v.z; r.w += v.w;
        }
        int jg = jt * 128 + jq * 4;
        float4 bb = *(const float4*)(b1 + e * HHH + jg);
        float4 o;
        o.x = gelu_exact(r.x + bb.x);
        o.y = gelu_exact(r.y + bb.y);
        o.z = gelu_exact(r.z + bb.z);
        o.w = gelu_exact(r.w + bb.w);
        *(float4*)(g_h + (size_t)(b * EE + e) * HHH + jg) = o;
    }
}

// ---------------- 5. MLP2 partial: grid (32 e, 8 hc of 512), 256 thr -------
// prologue reads g_h (L2-hot, gelu already applied)
__global__ void k_mlp2(const float* __restrict__ w2) {
    __shared__ float hs[4][512];                  // 8 KB
    int e = blockIdx.x, hc = blockIdx.y, t = threadIdx.x;
    #pragma unroll
    for (int k = 0; k < 8; k++) {
        int idx = t + k * 256;
        int b = idx >> 9, j = idx & 511;
        hs[b][j] = g_h[(size_t)(b * EE + e) * HHH + hc * 512 + j];
    }
    __syncthreads();
    int d0 = t * 4;
    const float4* wp = (const float4*)(w2 + ((size_t)e * HHH + hc * 512) * DD + d0);
    float4 a0 = {0,0,0,0}, a1 = {0,0,0,0}, a2 = {0,0,0,0}, a3 = {0,0,0,0};
    #pragma unroll 16
    for (int hh = 0; hh < 512; hh++) {
        float4 w = __ldcs(&wp[(size_t)hh * (DD / 4)]);
        float h0 = hs[0][hh], h1 = hs[1][hh], h2 = hs[2][hh], h3 = hs[3][hh];
        a0.x += h0 * w.x; a0.y += h0 * w.y; a0.z += h0 * w.z; a0.w += h0 * w.w;
        a1.x += h1 * w.x; a1.y += h1 * w.y; a1.z += h1 * w.z; a1.w += h1 * w.w;
        a2.x += h2 * w.x; a2.y += h2 * w.y; a2.z += h2 * w.z; a2.w += h2 * w.w;
        a3.x += h3 * w.x; a3.y += h3 * w.y; a3.z += h3 * w.z; a3.w += h3 * w.w;
    }
    float4* op = (float4*)(g_eout_part + (size_t)hc * (BB * EE * DD));
    op[((0 * EE + e) * DD + d0) >> 2] = a0;
    op[((1 * EE + e) * DD + d0) >> 2] = a1;
    op[((2 * EE + e) * DD + d0) >> 2] = a2;
    op[((3 * EE + e) * DD + d0) >> 2] = a3;
}

// ---------------- 6. eout = sum_hc eout_part + b2 --------------------------
__global__ void k_eout_reduce(const float* __restrict__ b2) {
    int i4 = blockIdx.x * 256 + threadIdx.x;   // 32768 float4s
    float4 acc = {0, 0, 0, 0};
    #pragma unroll
    for (int c = 0; c < 8; c++) {
        float4 v = ((const float4*)(g_eout_part + (size_t)c * (BB * EE * DD)))[i4];
        acc.x += v.x; acc.y += v.y; acc.z += v.z; acc.w += v.w;
    }
    int i = i4 << 2;
    int e = (i >> 10) & 31, d = i & 1023;
    float4 bb = *(const float4*)(b2 + e * DD + d);
    acc.x += bb.x; acc.y += bb.y; acc.z += bb.z; acc.w += bb.w;
    ((float4*)g_eout)[i4] = acc;
}

// ---------------- 7. out = combine @ eout, + metrics finalization ----------
__global__ void k_out(float* __restrict__ out, int out_size) {
    __shared__ float eo[32][256];
    __shared__ float cw[64][32];
    int b = blockIdx.x, nt = blockIdx.y, dt = blockIdx.z, t = threadIdx.x;
    #pragma unroll
    for (int k = 0; k < 32; k++) {
        int idx = t + k * 256;
        int e = idx >> 8, c = idx & 255;
        eo[e][c] = g_eout[(b * EE + e) * DD + dt * 256 + c];
    }
    #pragma unroll
    for (int k = 0; k < 8; k++) {
        int idx = t + k * 256;
        int r = idx >> 5, c = idx & 31;
        cw[r][c] = g_combine[(((b << 10) + nt * 64 + r) << 5) + c];
    }
    __syncthreads();
    int d = dt * 256 + t;
    for (int n = 0; n < 64; n++) {
        float a = 0.f;
        #pragma unroll
        for (int e = 0; e < 32; e++) a += cw[n][e] * eo[e][t];
        out[(((b << 10) + nt * 64 + n) << 10) + d] = a;
    }
    // metrics finalization in block 0 (all deps done before this kernel)
    if (blockIdx.x == 0 && blockIdx.y == 0 && blockIdx.z == 0) {
        float a = g_part_cw1[t] + g_part_cw1[t + 256];
        float bb = g_part_cw2[t] + g_part_cw2[t + 256];
        float c = (t < 128) ? g_part_dw[t] : 0.f;
        a = blockSum(a);
        bb = blockSum(bb);
        c = blockSum(c);
        if (t == 0) {
            out[out_size - 2] = (a - bb) / (float)(4.0 * 1024.0 * 1023.0);
            out[out_size - 1] = c / (float)(4 * 32 * 31);
        }
    }
}

// ---------------- launch ----------------
extern "C" void kernel_launch(void* const* d_in, const int* in_sizes, int n_in,
                              void* d_out, int out_size) {
    const float* x   = (const float*)d_in[0];
    const float* phi = (const float*)d_in[1];
    const float* kg  = (const float*)d_in[2];
    const float* kb  = (const float*)d_in[3];
    const float* qg  = (const float*)d_in[4];
    const float* qb  = (const float*)d_in[5];
    const float* lg  = (const float*)d_in[6];
    const float* lb  = (const float*)d_in[7];
    const float* sc  = (const float*)d_in[8];
    const float* w1  = (const float*)d_in[9];
    const float* b1  = (const float*)d_in[10];
    const float* w2  = (const float*)d_in[11];
    const float* b2  = (const float*)d_in[12];
    float* out = (float*)d_out;

    k_logits_q<<<64, 256>>>(x, phi, kg, kb, qg, qb, lg, lb, sc);  // 1
    k_softmaxes<<<640, 256>>>();                                   // 2 (dispatch+combine)
    k_slots<<<dim3(4, 16, 4), 256>>>(x);                           // 3
    k_mlp1<<<dim3(32, 32), 256>>>(w1, b1);                         // 4  <- ncu capture slot
    k_mlp2<<<dim3(32, 8), 256>>>(w2);                              // 5
    k_eout_reduce<<<128, 256>>>(b2);                               // 6
    k_out<<<dim3(4, 16, 4), 256>>>(out, out_size);                 // 7
}

// round 16
// speedup vs baseline: 1.1097x; 1.1097x over previous
#include <cuda_runtime.h>
#include <math.h>

#define BB 4
#define NN 1024
#define DD 1024
#define EE 32
#define HHH 4096

// ---------------- scratch (device globals; no allocation allowed) ----------
__device__ float g_logits[BB * NN * EE];            // 512 KB  [b,n,e]
__device__ float g_logitsT[BB * EE * NN];           // 512 KB  [b,e,n]
__device__ float g_combine[BB * NN * EE];           // 512 KB  [b,n,e]
__device__ float g_dispT[BB * EE * NN];             // 512 KB  [b,e,n]
__device__ float g_slots_part[4 * BB * EE * DD];    // 2 MB
__device__ float g_h[BB * EE * HHH];                // 2 MB
__device__ float g_eout_part[32 * BB * EE * DD];    // 16 MB
__device__ float g_eout[BB * EE * DD];              // 512 KB
__device__ float g_part_cw1[128];
__device__ float g_part_cw2[128];
__device__ float g_part_dw[128];

// ---------------- reduction helpers ----------------
__device__ __forceinline__ float warpSum(float v) {
    #pragma unroll
    for (int o = 16; o; o >>= 1) v += __shfl_xor_sync(0xffffffffu, v, o);
    return v;
}
__device__ __forceinline__ float warpMax(float v) {
    #pragma unroll
    for (int o = 16; o; o >>= 1) v = fmaxf(v, __shfl_xor_sync(0xffffffffu, v, o));
    return v;
}
__device__ float blockSum(float v) {
    __shared__ float sh[32];
    int lane = threadIdx.x & 31, wid = threadIdx.x >> 5;
    int nw = (blockDim.x + 31) >> 5;
    v = warpSum(v);
    if (lane == 0) sh[wid] = v;
    __syncthreads();
    float r = (threadIdx.x < (unsigned)nw) ? sh[threadIdx.x] : 0.f;
    if (wid == 0) {
        r = warpSum(r);
        if (lane == 0) sh[0] = r;
    }
    __syncthreads();
    r = sh[0];
    __syncthreads();
    return r;
}
__device__ float blockMax(float v) {
    __shared__ float sh[32];
    int lane = threadIdx.x & 31, wid = threadIdx.x >> 5;
    int nw = (blockDim.x + 31) >> 5;
    v = warpMax(v);
    if (lane == 0) sh[wid] = v;
    __syncthreads();
    float r = (threadIdx.x < (unsigned)nw) ? sh[threadIdx.x] : -INFINITY;
    if (wid == 0) {
        r = warpMax(r);
        if (lane == 0) sh[0] = r;
    }
    __syncthreads();
    r = sh[0];
    __syncthreads();
    return r;
}

__device__ __forceinline__ float gelu_exact(float x) {
    return 0.5f * x * (1.f + erff(x * 0.70710678118654752f));
}

// ---------------- 1. fused query-LN + logits (256 blocks x 16 n-rows) ------
// Each block recomputes LN stats for all 32 experts (phi is L2-hot), then
// computes logits[b, nb..nb+15, e] = sum_d (x*kg+kb)*q[e,d].
__global__ void k_logits_q(const float* __restrict__ x, const float* __restrict__ phi,
                           const float* __restrict__ kg, const float* __restrict__ kb,
                           const float* __restrict__ qg, const float* __restrict__ qb,
                           const float* __restrict__ lg, const float* __restrict__ lb,
                           const float* __restrict__ sc) {
    __shared__ float xs[16][64];
    __shared__ float qs[32][65];
    __shared__ float ts[16][33];
    __shared__ float s_mean[32], s_rs[32];
    int t = threadIdx.x;
    int b = blockIdx.x >> 6, nb = (blockIdx.x & 63) * 16;
    int e = t & 31, ng = t >> 5;
    int lane = t & 31, w = t >> 5;

    // LN stats: warp w handles experts w*4..w*4+3
    #pragma unroll
    for (int i = 0; i < 4; i++) {
        int ee = w * 4 + i;
        float s = 0.f, s2 = 0.f;
        #pragma unroll 8
        for (int k = 0; k < 32; k++) {
            int d = k * 32 + lane;
            float y = phi[ee * DD + d] * qg[d] + qb[d];
            s += y; s2 += y * y;
        }
        s = warpSum(s); s2 = warpSum(s2);
        if (lane == 0) {
            float m = s * (1.f / DD);
            s_mean[ee] = m;
            s_rs[ee] = rsqrtf(s2 * (1.f / DD) - m * m + 1e-5f);
        }
    }
    __syncthreads();
    float scale = sc[0];

    float acc[2] = {0, 0};
    for (int dc = 0; dc < 16; dc++) {
        int dbase = dc * 64;
        #pragma unroll
        for (int k = 0; k < 4; k++) {
            int idx = t + k * 256;
            int r = idx >> 6, c = idx & 63, d = dbase + c;
            xs[r][c] = x[((b << 10) + nb + r) * DD + d] * kg[d] + kb[d];
        }
        #pragma unroll
        for (int k = 0; k < 8; k++) {
            int idx = t + k * 256;
            int r = idx >> 6, c = idx & 63, d = dbase + c;
            float y = phi[r * DD + d] * qg[d] + qb[d];
            qs[r][c] = ((y - s_mean[r]) * s_rs[r] * lg[d] + lb[d]) * scale;
        }
        __syncthreads();
        #pragma unroll 4
        for (int dd = 0; dd < 64; dd++) {
            float qv = qs[e][dd];
            acc[0] += xs[ng * 2][dd] * qv;
            acc[1] += xs[ng * 2 + 1][dd] * qv;
        }
        __syncthreads();
    }
    #pragma unroll
    for (int i = 0; i < 2; i++) {
        g_logits[(((b << 10) + nb + ng * 2 + i) << 5) + e] = acc[i];
        ts[ng * 2 + i][e] = acc[i];
    }
    __syncthreads();
    #pragma unroll
    for (int k = 0; k < 2; k++) {
        int idx = t + k * 256;
        int ee = idx >> 4, n = idx & 15;
        g_logitsT[(((b << 5) + ee) << 10) + nb + n] = ts[n][ee];
    }
}

// ---------------- 2. dispatch softmax over N (coalesced) -------------------
__global__ void k_dispatch_sm() {
    int be = blockIdx.x;          // be = b*32 + e
    int e = be & 31;
    int t = threadIdx.x;
    float v[4];
    float mx = -INFINITY;
    #pragma unroll
    for (int k = 0; k < 4; k++) {
        int n = t + k * 256;
        v[k] = g_logitsT[(be << 10) + n];
        mx = fmaxf(mx, v[k]);
    }
    mx = blockMax(mx);
    float ls = 0.f;
    #pragma unroll
    for (int k = 0; k < 4; k++) { v[k] = expf(v[k] - mx); ls += v[k]; }
    float S = blockSum(ls);
    float inv = 1.f / S;
    float s1 = 0.f, s2 = 0.f;
    #pragma unroll
    for (int k = 0; k < 4; k++) {
        int n = t + k * 256;
        float dv = v[k] * inv;
        g_dispT[(be << 10) + n] = dv;
        s1 += dv;
        s2 += dv * dv;
    }
    float S1 = blockSum(s1);
    float S2 = blockSum(s2);
    if (t == 0) {
        float rsd = rsqrtf(S2 + 1e-9f);
        float sn = S1 * rsd;
        g_part_dw[be] = (e == 0) ? 0.f : sn * sn;
    }
}

// ---------------- 3. slots partials: sum_n dispT[b,e,n]*x[b,n,d] -----------
__global__ void k_slots(const float* __restrict__ x) {
    __shared__ float ws[64][33];
    int b = blockIdx.x, dt = blockIdx.y, nc = blockIdx.z;
    int t = threadIdx.x;
    int d = dt * 64 + (t & 63);
    int eb = (t >> 6) * 8;
    float acc[8] = {0, 0, 0, 0, 0, 0, 0, 0};
    for (int no = 0; no < 4; no++) {
        int nbase = nc * 256 + no * 64;
        #pragma unroll
        for (int k = 0; k < 8; k++) {
            int idx = t + k * 256;
            int ee = idx >> 6, n = idx & 63;
            ws[n][ee] = g_dispT[(((b << 5) + ee) << 10) + nbase + n];
        }
        __syncthreads();
        #pragma unroll 4
        for (int nn = 0; nn < 64; nn++) {
            float xv = __ldg(&x[(((b << 10) + nbase + nn) << 10) + d]);
            #pragma unroll
            for (int i = 0; i < 8; i++) acc[i] += ws[nn][eb + i] * xv;
        }
        __syncthreads();
    }
    #pragma unroll
    for (int i = 0; i < 8; i++)
        g_slots_part[nc * (BB * EE * DD) + (b * EE + eb + i) * DD + d] = acc[i];
}

// ---------------- 4. MLP1: h = gelu(slots @ w1 + b1), direct write ---------
// grid (32 e, 32 jt of 128), 256 thr. Warp dg handles d = dg mod 8;
// cross-warp reduce in smem, then b1 + gelu epilogue.
__global__ void k_mlp1(const float* __restrict__ w1, const float* __restrict__ b1) {
    __shared__ float ss[4][1024];                 // 16 KB
    __shared__ float4 red[8][32][4];              // 16 KB
    int e = blockIdx.x, jt = blockIdx.y, t = threadIdx.x;
    // prologue: fuse slots nc-reduce (slots_part is L2-resident)
    #pragma unroll
    for (int k = 0; k < 16; k++) {
        int idx = t + k * 256;
        int b = idx >> 10, d = idx & 1023;
        float s = 0.f;
        #pragma unroll
        for (int nc = 0; nc < 4; nc++)
            s += g_slots_part[nc * (BB * EE * DD) + (b * EE + e) * DD + d];
        ss[b][d] = s;
    }
    __syncthreads();
    int lane = t & 31, dg = t >> 5;
    int j = jt * 128 + lane * 4;
    const float* wbase = w1 + (size_t)e * DD * HHH;
    float4 a0 = {0,0,0,0}, a1 = {0,0,0,0}, a2 = {0,0,0,0}, a3 = {0,0,0,0};
    #pragma unroll 8
    for (int d = dg; d < 1024; d += 8) {
        float4 w = __ldcs((const float4*)(wbase + (size_t)d * HHH + j));
        float s0 = ss[0][d], s1 = ss[1][d], s2 = ss[2][d], s3 = ss[3][d];
        a0.x += s0 * w.x; a0.y += s0 * w.y; a0.z += s0 * w.z; a0.w += s0 * w.w;
        a1.x += s1 * w.x; a1.y += s1 * w.y; a1.z += s1 * w.z; a1.w += s1 * w.w;
        a2.x += s2 * w.x; a2.y += s2 * w.y; a2.z += s2 * w.z; a2.w += s2 * w.w;
        a3.x += s3 * w.x; a3.y += s3 * w.y; a3.z += s3 * w.z; a3.w += s3 * w.w;
    }
    red[dg][lane][0] = a0;
    red[dg][lane][1] = a1;
    red[dg][lane][2] = a2;
    red[dg][lane][3] = a3;
    __syncthreads();
    if (t < 128) {
        int b = t >> 5, jq = t & 31;
        float4 r = {0,0,0,0};
        #pragma unroll
        for (int g = 0; g < 8; g++) {
            float4 v = red[g][jq][b];
            r.x += v.x; r.y += v.y; r.z += v.z; r.w += v.w;
        }
        int jg = jt * 128 + jq * 4;
        float4 bb = *(const float4*)(b1 + e * HHH + jg);
        float4 o;
        o.x = gelu_exact(r.x + bb.x);
        o.y = gelu_exact(r.y + bb.y);
        o.z = gelu_exact(r.z + bb.z);
        o.w = gelu_exact(r.w + bb.w);
        *(float4*)(g_h + (size_t)(b * EE + e) * HHH + jg) = o;
    }
}

// ---------------- 5. combine softmax + cw metric partials ------------------
__global__ void k_combine_sm() {
    int t = threadIdx.x, lane = t & 31, w = t >> 5;
    int row = blockIdx.x * 32 + w;
    float v = g_logits[(row << 5) + lane];
    float m = warpMax(v);
    float p = expf(v - m);
    float s = warpSum(p);
    float cw = p / s;
    g_combine[(row << 5) + lane] = cw;
    float s2 = warpSum(cw * cw);
    float rs = rsqrtf(s2 + 1e-9f);
    float cf = cw * rs;
    float s1 = warpSum(cf);
    int n = row & 1023;
    float c2 = (n < 32 && lane == n) ? cf * s1 : 0.f;
    c2 = warpSum(c2);
    __shared__ float p1[32], p2[32];
    if (lane == 0) { p1[w] = s1 * s1; p2[w] = c2; }
    __syncthreads();
    if (w == 0) {
        float a = warpSum(p1[lane]);
        float bb2 = warpSum(p2[lane]);
        if (lane == 0) { g_part_cw1[blockIdx.x] = a; g_part_cw2[blockIdx.x] = bb2; }
    }
}

// ---------------- 6. MLP2 partial: grid (32 e, 32 hc), 256 thr -------------
// prologue reads g_h (L2-hot, gelu already applied)
__global__ void k_mlp2(const float* __restrict__ w2) {
    __shared__ float hs[4][128];
    int e = blockIdx.x, hc = blockIdx.y, t = threadIdx.x;
    #pragma unroll
    for (int k = 0; k < 2; k++) {
        int idx = t + k * 256;
        int b = idx >> 7, j = idx & 127;
        hs[b][j] = g_h[(size_t)(b * EE + e) * HHH + hc * 128 + j];
    }
    __syncthreads();
    int d0 = t * 4;
    const float4* wp = (const float4*)(w2 + ((size_t)e * HHH + hc * 128) * DD + d0);
    float4 a0 = {0,0,0,0}, a1 = {0,0,0,0}, a2 = {0,0,0,0}, a3 = {0,0,0,0};
    #pragma unroll 16
    for (int hh = 0; hh < 128; hh++) {
        float4 w = __ldcs(&wp[(size_t)hh * (DD / 4)]);
        float h0 = hs[0][hh], h1 = hs[1][hh], h2 = hs[2][hh], h3 = hs[3][hh];
        a0.x += h0 * w.x; a0.y += h0 * w.y; a0.z += h0 * w.z; a0.w += h0 * w.w;
        a1.x += h1 * w.x; a1.y += h1 * w.y; a1.z += h1 * w.z; a1.w += h1 * w.w;
        a2.x += h2 * w.x; a2.y += h2 * w.y; a2.z += h2 * w.z; a2.w += h2 * w.w;
        a3.x += h3 * w.x; a3.y += h3 * w.y; a3.z += h3 * w.z; a3.w += h3 * w.w;
    }
    float4* op = (float4*)(g_eout_part + (size_t)hc * (BB * EE * DD));
    op[((0 * EE + e) * DD + d0) >> 2] = a0;
    op[((1 * EE + e) * DD + d0) >> 2] = a1;
    op[((2 * EE + e) * DD + d0) >> 2] = a2;
    op[((3 * EE + e) * DD + d0) >> 2] = a3;
}

// ---------------- 7. eout = sum_hc eout_part + b2 --------------------------
__global__ void k_eout_reduce(const float* __restrict__ b2) {
    int i4 = blockIdx.x * 256 + threadIdx.x;   // 32768 float4s
    float4 acc = {0, 0, 0, 0};
    #pragma unroll
    for (int c = 0; c < 32; c++) {
        float4 v = ((const float4*)(g_eout_part + (size_t)c * (BB * EE * DD)))[i4];
        acc.x += v.x; acc.y += v.y; acc.z += v.z; acc.w += v.w;
    }
    int i = i4 << 2;
    int e = (i >> 10) & 31, d = i & 1023;
    float4 bb = *(const float4*)(b2 + e * DD + d);
    acc.x += bb.x; acc.y += bb.y; acc.z += bb.z; acc.w += bb.w;
    ((float4*)g_eout)[i4] = acc;
}

// ---------------- 8. out = combine @ eout, + metrics finalization ----------
__global__ void k_out(float* __restrict__ out, int out_size) {
    __shared__ float eo[32][256];
    __shared__ float cw[64][32];
    int b = blockIdx.x, nt = blockIdx.y, dt = blockIdx.z, t = threadIdx.x;
    #pragma unroll
    for (int k = 0; k < 32; k++) {
        int idx = t + k * 256;
        int e = idx >> 8, c = idx & 255;
        eo[e][c] = g_eout[(b * EE + e) * DD + dt * 256 + c];
    }
    #pragma unroll
    for (int k = 0; k < 8; k++) {
        int idx = t + k * 256;
        int r = idx >> 5, c = idx & 31;
        cw[r][c] = g_combine[(((b << 10) + nt * 64 + r) << 5) + c];
    }
    __syncthreads();
    int d = dt * 256 + t;
    for (int n = 0; n < 64; n++) {
        float a = 0.f;
        #pragma unroll
        for (int e = 0; e < 32; e++) a += cw[n][e] * eo[e][t];
        out[(((b << 10) + nt * 64 + n) << 10) + d] = a;
    }
    // metrics finalization in block 0 (all deps done before this kernel)
    if (blockIdx.x == 0 && blockIdx.y == 0 && blockIdx.z == 0) {
        float a = (t < 128) ? g_part_cw1[t] : 0.f;
        float bb = (t < 128) ? g_part_cw2[t] : 0.f;
        float c = (t < 128) ? g_part_dw[t] : 0.f;
        a = blockSum(a);
        bb = blockSum(bb);
        c = blockSum(c);
        if (t == 0) {
            out[out_size - 2] = (a - bb) / (float)(4.0 * 1024.0 * 1023.0);
            out[out_size - 1] = c / (float)(4 * 32 * 31);
        }
    }
}

// ---------------- launch ----------------
extern "C" void kernel_launch(void* const* d_in, const int* in_sizes, int n_in,
                              void* d_out, int out_size) {
    const float* x   = (const float*)d_in[0];
    const float* phi = (const float*)d_in[1];
    const float* kg  = (const float*)d_in[2];
    const float* kb  = (const float*)d_in[3];
    const float* qg  = (const float*)d_in[4];
    const float* qb  = (const float*)d_in[5];
    const float* lg  = (const float*)d_in[6];
    const float* lb  = (const float*)d_in[7];
    const float* sc  = (const float*)d_in[8];
    const float* w1  = (const float*)d_in[9];
    const float* b1  = (const float*)d_in[10];
    const float* w2  = (const float*)d_in[11];
    const float* b2  = (const float*)d_in[12];
    float* out = (float*)d_out;

    k_logits_q<<<256, 256>>>(x, phi, kg, kb, qg, qb, lg, lb, sc); // 1 (widened grid)
    k_dispatch_sm<<<128, 256>>>();                                 // 2
    k_slots<<<dim3(4, 16, 4), 256>>>(x);                           // 3
    k_mlp1<<<dim3(32, 32), 256>>>(w1, b1);                         // 4  <- ncu capture slot
    k_combine_sm<<<128, 1024>>>();                                 // 5
    k_mlp2<<<dim3(32, 32), 256>>>(w2);                             // 6
    k_eout_reduce<<<128, 256>>>(b2);                               // 7
    k_out<<<dim3(4, 16, 4), 256>>>(out, out_size);                 // 8
}